// round 8
// baseline (speedup 1.0000x reference)
#include <cuda_runtime.h>
#include <cuda_bf16.h>
#include <math.h>
#include <stdint.h>

// Problem constants (fixed by the dataset)
#define T_TOK 8192
#define D_DIM 1024
#define E_EXP 8
#define H_DIM 4096

// ---------------- device-global scratch ----------------
__device__ int   g_cnt[E_EXP];
__device__ int   g_off[E_EXP];
__device__ int   g_tok[E_EXP * T_TOK];
__device__ float g_wt [E_EXP * T_TOK];
__device__ float g_h  [(size_t)T_TOK * 2 * H_DIM];   // fp32 hidden scratch (256MB)

// ---------------- helpers ----------------
__device__ __forceinline__ uint32_t smem_u32(const void* p) {
    uint32_t a;
    asm("{ .reg .u64 t; cvta.to.shared.u64 t, %1; cvt.u32.u64 %0, t; }" : "=r"(a) : "l"(p));
    return a;
}
__device__ __forceinline__ void ldsm4(uint32_t* r, uint32_t addr) {
    asm volatile("ldmatrix.sync.aligned.m8n8.x4.shared.b16 {%0,%1,%2,%3}, [%4];"
                 : "=r"(r[0]), "=r"(r[1]), "=r"(r[2]), "=r"(r[3]) : "r"(addr));
}
__device__ __forceinline__ void mma_bf16(float* c, const uint32_t* a, const uint32_t* b) {
    asm volatile("mma.sync.aligned.m16n8k16.row.col.f32.bf16.bf16.f32 "
                 "{%0,%1,%2,%3}, {%4,%5,%6,%7}, {%8,%9}, {%0,%1,%2,%3};"
                 : "+f"(c[0]), "+f"(c[1]), "+f"(c[2]), "+f"(c[3])
                 : "r"(a[0]), "r"(a[1]), "r"(a[2]), "r"(a[3]), "r"(b[0]), "r"(b[1]));
}
// pack {lo=bf16(a), hi=bf16(b)} in one cvt
__device__ __forceinline__ uint32_t cvt2(float a, float b) {
    uint32_t r;
    asm("cvt.rn.bf16x2.f32 %0, %1, %2;" : "=r"(r) : "f"(b), "f"(a));
    return r;
}
__device__ __forceinline__ float gelu_exact(float v) {
    return 0.5f * v * (1.0f + erff(v * 0.70710678118654752f));
}

// ---------------- small kernels (R1-proven) ----------------
__global__ void zero_kernel(float* __restrict__ out, int n) {
    int i = blockIdx.x * blockDim.x + threadIdx.x;
    if (i < E_EXP) g_cnt[i] = 0;
    for (int j = i; j < n; j += gridDim.x * blockDim.x) out[j] = 0.0f;
}

__global__ void router_kernel(const float* __restrict__ x, const float* __restrict__ Wg) {
    int warp = (blockIdx.x * blockDim.x + threadIdx.x) >> 5;
    int lane = threadIdx.x & 31;
    if (warp >= T_TOK) return;
    const float* xr = x + (size_t)warp * D_DIM;
    float acc[E_EXP];
#pragma unroll
    for (int e = 0; e < E_EXP; e++) acc[e] = 0.0f;
    for (int k = lane; k < D_DIM; k += 32) {
        float xv = xr[k];
        const float* wr = Wg + (size_t)k * E_EXP;
#pragma unroll
        for (int e = 0; e < E_EXP; e++) acc[e] = fmaf(xv, wr[e], acc[e]);
    }
#pragma unroll
    for (int e = 0; e < E_EXP; e++)
#pragma unroll
        for (int o = 16; o > 0; o >>= 1) acc[e] += __shfl_xor_sync(0xffffffffu, acc[e], o);
    if (lane == 0) {
        float mx = acc[0];
#pragma unroll
        for (int e = 1; e < E_EXP; e++) mx = fmaxf(mx, acc[e]);
        float p[E_EXP], s = 0.0f;
#pragma unroll
        for (int e = 0; e < E_EXP; e++) { p[e] = expf(acc[e] - mx); s += p[e]; }
        float inv = 1.0f / s;
        int i1 = 0; float v1 = p[0];
#pragma unroll
        for (int e = 1; e < E_EXP; e++) if (p[e] > v1) { v1 = p[e]; i1 = e; }
        int i2 = -1; float v2 = -1.0f;
#pragma unroll
        for (int e = 0; e < E_EXP; e++) if (e != i1 && p[e] > v2) { v2 = p[e]; i2 = e; }
        int p1 = atomicAdd(&g_cnt[i1], 1);
        g_tok[i1 * T_TOK + p1] = warp; g_wt[i1 * T_TOK + p1] = v1 * inv;
        int p2 = atomicAdd(&g_cnt[i2], 1);
        g_tok[i2 * T_TOK + p2] = warp; g_wt[i2 * T_TOK + p2] = v2 * inv;
    }
}

__global__ void scan_kernel() {
    if (threadIdx.x == 0) {
        int s = 0;
#pragma unroll
        for (int e = 0; e < E_EXP; e++) { g_off[e] = s; s += g_cnt[e]; }
    }
}

// ---------------- HMMA GEMM, 64x64 warp tiles, inline fp32->bf16 hi/lo ----------------
// Sub-stage (16KB): 128 rows x 128B. Row r, 8 chunks of 16B at slot ((c ^ (r&7)) << 4):
//   c0,c1: A_hi k0-7,k8-15 | c2,c3: A_lo | c4,c5: B_hi | c6,c7: B_lo
// Stage (32KB) = 2 sub-stages (k 0-15, k 16-31). 2 stages double-buffered = 64KB.
// CTA tile 128x128, 128 threads, 4 warps in 2x2, each warp 64x64.
#define BM 128
#define BN 128
#define SUB_BYTES 16384
#define STAGE_BYTES 32768

__device__ __forceinline__ void load_A16(float* f, const float* a) {
    const float4* p = (const float4*)a;
#pragma unroll
    for (int q = 0; q < 4; q++) {
        float4 v = p[q];
        f[4 * q] = v.x; f[4 * q + 1] = v.y; f[4 * q + 2] = v.z; f[4 * q + 3] = v.w;
    }
}
__device__ __forceinline__ void load_B16(float* f, const float* b, int stride) {
#pragma unroll
    for (int k = 0; k < 16; k++) f[k] = __ldg(b + (size_t)k * stride);
}

// convert 16 fp32 -> hi/lo bf16 chunks, store into sub-stage row r at chunk base cbase (0=A,4=B)
__device__ __forceinline__ void cvt_store_row(uint32_t sb, int r, int cbase, const float* f) {
    uint32_t rb = sb + (uint32_t)r * 128;
    uint32_t rx = (uint32_t)(r & 7);
#pragma unroll
    for (int half = 0; half < 2; half++) {
        uint32_t hi[4], lo[4];
#pragma unroll
        for (int q = 0; q < 4; q++) {
            float a = f[half * 8 + 2 * q], b = f[half * 8 + 2 * q + 1];
            uint32_t h = cvt2(a, b);
            float ha = __uint_as_float(h << 16);
            float hb = __uint_as_float(h & 0xFFFF0000u);
            hi[q] = h;
            lo[q] = cvt2(a - ha, b - hb);
        }
        uint32_t ah = rb + ((((uint32_t)(cbase + half)) ^ rx) << 4);
        uint32_t al = rb + ((((uint32_t)(cbase + 2 + half)) ^ rx) << 4);
        asm volatile("st.shared.v4.b32 [%0], {%1,%2,%3,%4};"
                     :: "r"(ah), "r"(hi[0]), "r"(hi[1]), "r"(hi[2]), "r"(hi[3]));
        asm volatile("st.shared.v4.b32 [%0], {%1,%2,%3,%4};"
                     :: "r"(al), "r"(lo[0]), "r"(lo[1]), "r"(lo[2]), "r"(lo[3]));
    }
}

// one k16 sub-stage; acc[32][4] = [mt*8 + ntile][frag], warp tile 64x64
__device__ __forceinline__ void compute_sub(uint32_t sb, float acc[32][4]) {
    int tid = threadIdx.x;
    int lane = tid & 31;
    int wid = tid >> 5;
    int wm = (wid & 1) * 64;
    int wn = (wid >> 1) * 64;
    int g = lane >> 3, lr = lane & 7;

    int aRow0 = wm + ((g & 1) << 3) + lr;
    uint32_t ah = (uint32_t)(g >> 1);
    int bRow0 = wn + ((g >> 1) << 3) + lr;
    uint32_t bh_ = (uint32_t)(g & 1);

    uint32_t Ah[4][4], Al[4][4];
#pragma unroll
    for (int mt = 0; mt < 4; mt++) {
        uint32_t row = (uint32_t)(aRow0 + 16 * mt);
        uint32_t rb = sb + row * 128, rx = row & 7;
        ldsm4(Ah[mt], rb + (((0u + ah) ^ rx) << 4));
        ldsm4(Al[mt], rb + (((2u + ah) ^ rx) << 4));
    }
#pragma unroll
    for (int half = 0; half < 2; half++) {
        uint32_t Bh[8], Bl[8];
#pragma unroll
        for (int p = 0; p < 2; p++) {
            uint32_t row = (uint32_t)(bRow0 + 16 * (half * 2 + p));
            uint32_t rb = sb + row * 128, rx = row & 7;
            ldsm4(&Bh[4 * p], rb + (((4u + bh_) ^ rx) << 4));
            ldsm4(&Bl[4 * p], rb + (((6u + bh_) ^ rx) << 4));
        }
#pragma unroll
        for (int mt = 0; mt < 4; mt++)
#pragma unroll
            for (int jj = 0; jj < 4; jj++) {
                float* c = acc[mt * 8 + half * 4 + jj];
                const uint32_t* bp  = &Bh[(jj >> 1) * 4 + (jj & 1) * 2];
                const uint32_t* blp = &Bl[(jj >> 1) * 4 + (jj & 1) * 2];
                mma_bf16(c, Ah[mt], bp);     // hi*hi
                mma_bf16(c, Ah[mt], blp);    // hi*lo
                mma_bf16(c, Al[mt], bp);     // lo*hi
            }
    }
}

// interleaved 32-k mainloop: KT2 stages of 32 k-values, one barrier per stage.
// Each thread loads A row tid AND B row tid.
template <int KT2>
__device__ __forceinline__ void gemm_mainloop(uint32_t sbase, int r,
                                              const float* srcA, const float* srcB, int strideB,
                                              float acc[32][4]) {
    {   // prologue: fill buffer 0 (both sub-stages)
        float f[16];
        load_A16(f, srcA);                       cvt_store_row(sbase, r, 0, f);
        load_B16(f, srcB, strideB);              cvt_store_row(sbase, r, 4, f);
        load_A16(f, srcA + 16);                  cvt_store_row(sbase + SUB_BYTES, r, 0, f);
        load_B16(f, srcB + (size_t)16 * strideB, strideB); cvt_store_row(sbase + SUB_BYTES, r, 4, f);
    }
    __syncthreads();
    for (int kt = 0; kt < KT2; kt++) {
        uint32_t cur = sbase + (uint32_t)(kt & 1) * STAGE_BYTES;
        uint32_t nxt = sbase + (uint32_t)((kt + 1) & 1) * STAGE_BYTES;
        bool more = (kt + 1 < KT2);
        if (more) {
            float fn[16];
            int k0 = (kt + 1) * 32;
            load_A16(fn, srcA + k0);             cvt_store_row(nxt, r, 0, fn);
            load_B16(fn, srcB + (size_t)k0 * strideB, strideB); cvt_store_row(nxt, r, 4, fn);
        }
        compute_sub(cur, acc);
        if (more) {
            float fn[16];
            int k0 = (kt + 1) * 32 + 16;
            load_A16(fn, srcA + k0);             cvt_store_row(nxt + SUB_BYTES, r, 0, fn);
            load_B16(fn, srcB + (size_t)k0 * strideB, strideB); cvt_store_row(nxt + SUB_BYTES, r, 4, fn);
        }
        compute_sub(cur + SUB_BYTES, acc);
        __syncthreads();
    }
}

// GEMM1: h = gelu(x[tok] @ W1[e] + b1) -> g_h (fp32)
__global__ __launch_bounds__(128, 2)
void gemm1_kernel(const float* __restrict__ x, const float* __restrict__ W1,
                  const float* __restrict__ b1) {
    __shared__ __align__(128) char smem[2 * STAGE_BYTES];
    int e = blockIdx.z;
    int cnt = g_cnt[e];
    int row0 = blockIdx.y * BM;
    if (row0 >= cnt) return;
    int col0 = blockIdx.x * BN;
    int off = g_off[e];
    int tid = threadIdx.x;
    uint32_t sbase = smem_u32(smem);

    int rA = min(row0 + tid, cnt - 1);
    const float* srcA = x + (size_t)g_tok[e * T_TOK + rA] * D_DIM;
    const float* srcB = W1 + (size_t)e * D_DIM * H_DIM + col0 + tid;   // col, stride H over k

    float acc[32][4];
#pragma unroll
    for (int i = 0; i < 32; i++)
#pragma unroll
        for (int j = 0; j < 4; j++) acc[i][j] = 0.0f;

    gemm_mainloop<D_DIM / 32>(sbase, tid, srcA, srcB, H_DIM, acc);

    // epilogue: bias + gelu -> g_h fp32
    int lane = tid & 31, wid = tid >> 5;
    int wm = (wid & 1) * 64, wn = (wid >> 1) * 64;
    int mrow = row0 + wm + (lane >> 2);
    int ncol = col0 + wn + (lane & 3) * 2;
    const float* bg = b1 + (size_t)e * H_DIM;

#pragma unroll
    for (int mt = 0; mt < 4; mt++)
#pragma unroll
        for (int nt = 0; nt < 8; nt++) {
            float* c = acc[mt * 8 + nt];
            int cc = ncol + nt * 8;
            float bias0 = bg[cc], bias1 = bg[cc + 1];
            int r1 = mrow + mt * 16, r2 = r1 + 8;
            if (r1 < cnt) {
                size_t o = (size_t)(off + r1) * H_DIM + cc;
                *(float2*)(g_h + o) = make_float2(gelu_exact(c[0] + bias0), gelu_exact(c[1] + bias1));
            }
            if (r2 < cnt) {
                size_t o = (size_t)(off + r2) * H_DIM + cc;
                *(float2*)(g_h + o) = make_float2(gelu_exact(c[2] + bias0), gelu_exact(c[3] + bias1));
            }
        }
}

// GEMM2: out[tok] += w * (h @ W2[e] + b2)
__global__ __launch_bounds__(128, 2)
void gemm2_kernel(const float* __restrict__ W2, const float* __restrict__ b2,
                  float* __restrict__ out) {
    __shared__ __align__(128) char smem[2 * STAGE_BYTES];
    int e = blockIdx.z;
    int cnt = g_cnt[e];
    int row0 = blockIdx.y * BM;
    if (row0 >= cnt) return;
    int col0 = blockIdx.x * BN;
    int off = g_off[e];
    int tid = threadIdx.x;
    uint32_t sbase = smem_u32(smem);

    int rA = off + min(row0 + tid, cnt - 1);
    const float* srcA = g_h + (size_t)rA * H_DIM;
    const float* srcB = W2 + (size_t)e * H_DIM * D_DIM + col0 + tid;   // col, stride D over k

    float acc[32][4];
#pragma unroll
    for (int i = 0; i < 32; i++)
#pragma unroll
        for (int j = 0; j < 4; j++) acc[i][j] = 0.0f;

    gemm_mainloop<H_DIM / 32>(sbase, tid, srcA, srcB, D_DIM, acc);

    int lane = tid & 31, wid = tid >> 5;
    int wm = (wid & 1) * 64, wn = (wid >> 1) * 64;
    int mrow = row0 + wm + (lane >> 2);
    int ncol = col0 + wn + (lane & 3) * 2;
    const float* bg = b2 + (size_t)e * D_DIM;

#pragma unroll
    for (int mt = 0; mt < 4; mt++) {
        int r1 = mrow + mt * 16, r2 = r1 + 8;
        int tok1 = 0, tok2 = 0; float w1 = 0.0f, w2 = 0.0f;
        if (r1 < cnt) { tok1 = g_tok[e * T_TOK + r1]; w1 = g_wt[e * T_TOK + r1]; }
        if (r2 < cnt) { tok2 = g_tok[e * T_TOK + r2]; w2 = g_wt[e * T_TOK + r2]; }
#pragma unroll
        for (int nt = 0; nt < 8; nt++) {
            float* c = acc[mt * 8 + nt];
            int cc = ncol + nt * 8;
            float bias0 = bg[cc], bias1 = bg[cc + 1];
            if (r1 < cnt) {
                float* o = out + (size_t)tok1 * D_DIM + cc;
                atomicAdd(o,     w1 * (c[0] + bias0));
                atomicAdd(o + 1, w1 * (c[1] + bias1));
            }
            if (r2 < cnt) {
                float* o = out + (size_t)tok2 * D_DIM + cc;
                atomicAdd(o,     w2 * (c[2] + bias0));
                atomicAdd(o + 1, w2 * (c[3] + bias1));
            }
        }
    }
}

// ---------------- launch ----------------
extern "C" void kernel_launch(void* const* d_in, const int* in_sizes, int n_in,
                              void* d_out, int out_size) {
    const float* x  = (const float*)d_in[0];
    const float* Wg = (const float*)d_in[1];
    const float* W1 = (const float*)d_in[2];
    const float* b1 = (const float*)d_in[3];
    const float* W2 = (const float*)d_in[4];
    const float* b2 = (const float*)d_in[5];
    float* out = (float*)d_out;

    zero_kernel<<<4096, 256>>>(out, out_size);
    router_kernel<<<T_TOK / 8, 256>>>(x, Wg);
    scan_kernel<<<1, 32>>>();

    gemm1_kernel<<<dim3(H_DIM / BN, T_TOK / BM, E_EXP), 128>>>(x, W1, b1);
    gemm2_kernel<<<dim3(D_DIM / BN, T_TOK / BM, E_EXP), 128>>>(W2, b2, out);
}

// round 9
// speedup vs baseline: 1.1165x; 1.1165x over previous
#include <cuda_runtime.h>
#include <cuda_bf16.h>
#include <math.h>
#include <stdint.h>

// Problem constants (fixed by the dataset)
#define T_TOK 8192
#define D_DIM 1024
#define E_EXP 8
#define H_DIM 4096

// ---------------- device-global scratch ----------------
__device__ int   g_cnt[E_EXP];
__device__ int   g_off[E_EXP];
__device__ int   g_tok[E_EXP * T_TOK];
__device__ float g_wt [E_EXP * T_TOK];
__device__ float g_h  [(size_t)T_TOK * 2 * H_DIM];   // fp32 hidden scratch (256MB)

// ---------------- helpers ----------------
__device__ __forceinline__ uint32_t smem_u32(const void* p) {
    uint32_t a;
    asm("{ .reg .u64 t; cvta.to.shared.u64 t, %1; cvt.u32.u64 %0, t; }" : "=r"(a) : "l"(p));
    return a;
}
__device__ __forceinline__ void ldsm4(uint32_t* r, uint32_t addr) {
    asm volatile("ldmatrix.sync.aligned.m8n8.x4.shared.b16 {%0,%1,%2,%3}, [%4];"
                 : "=r"(r[0]), "=r"(r[1]), "=r"(r[2]), "=r"(r[3]) : "r"(addr));
}
__device__ __forceinline__ void mma_bf16(float* c, const uint32_t* a, const uint32_t* b) {
    asm volatile("mma.sync.aligned.m16n8k16.row.col.f32.bf16.bf16.f32 "
                 "{%0,%1,%2,%3}, {%4,%5,%6,%7}, {%8,%9}, {%0,%1,%2,%3};"
                 : "+f"(c[0]), "+f"(c[1]), "+f"(c[2]), "+f"(c[3])
                 : "r"(a[0]), "r"(a[1]), "r"(a[2]), "r"(a[3]), "r"(b[0]), "r"(b[1]));
}
// pack {lo=bf16(a), hi=bf16(b)} in one cvt
__device__ __forceinline__ uint32_t cvt2(float a, float b) {
    uint32_t r;
    asm("cvt.rn.bf16x2.f32 %0, %1, %2;" : "=r"(r) : "f"(b), "f"(a));
    return r;
}
__device__ __forceinline__ float gelu_exact(float v) {
    return 0.5f * v * (1.0f + erff(v * 0.70710678118654752f));
}

// ---------------- small kernels (R1-proven) ----------------
__global__ void zero_kernel(float* __restrict__ out, int n) {
    int i = blockIdx.x * blockDim.x + threadIdx.x;
    if (i < E_EXP) g_cnt[i] = 0;
    for (int j = i; j < n; j += gridDim.x * blockDim.x) out[j] = 0.0f;
}

__global__ void router_kernel(const float* __restrict__ x, const float* __restrict__ Wg) {
    int warp = (blockIdx.x * blockDim.x + threadIdx.x) >> 5;
    int lane = threadIdx.x & 31;
    if (warp >= T_TOK) return;
    const float* xr = x + (size_t)warp * D_DIM;
    float acc[E_EXP];
#pragma unroll
    for (int e = 0; e < E_EXP; e++) acc[e] = 0.0f;
    for (int k = lane; k < D_DIM; k += 32) {
        float xv = xr[k];
        const float* wr = Wg + (size_t)k * E_EXP;
#pragma unroll
        for (int e = 0; e < E_EXP; e++) acc[e] = fmaf(xv, wr[e], acc[e]);
    }
#pragma unroll
    for (int e = 0; e < E_EXP; e++)
#pragma unroll
        for (int o = 16; o > 0; o >>= 1) acc[e] += __shfl_xor_sync(0xffffffffu, acc[e], o);
    if (lane == 0) {
        float mx = acc[0];
#pragma unroll
        for (int e = 1; e < E_EXP; e++) mx = fmaxf(mx, acc[e]);
        float p[E_EXP], s = 0.0f;
#pragma unroll
        for (int e = 0; e < E_EXP; e++) { p[e] = expf(acc[e] - mx); s += p[e]; }
        float inv = 1.0f / s;
        int i1 = 0; float v1 = p[0];
#pragma unroll
        for (int e = 1; e < E_EXP; e++) if (p[e] > v1) { v1 = p[e]; i1 = e; }
        int i2 = -1; float v2 = -1.0f;
#pragma unroll
        for (int e = 0; e < E_EXP; e++) if (e != i1 && p[e] > v2) { v2 = p[e]; i2 = e; }
        int p1 = atomicAdd(&g_cnt[i1], 1);
        g_tok[i1 * T_TOK + p1] = warp; g_wt[i1 * T_TOK + p1] = v1 * inv;
        int p2 = atomicAdd(&g_cnt[i2], 1);
        g_tok[i2 * T_TOK + p2] = warp; g_wt[i2 * T_TOK + p2] = v2 * inv;
    }
}

__global__ void scan_kernel() {
    if (threadIdx.x == 0) {
        int s = 0;
#pragma unroll
        for (int e = 0; e < E_EXP; e++) { g_off[e] = s; s += g_cnt[e]; }
    }
}

// ---------------- HMMA GEMM with inline fp32 -> bf16 hi/lo split ----------------
// Sub-stage (16KB): 128 rows x 128B. Row r, 8 chunks of 16B at slot ((c ^ (r&7)) << 4):
//   c0,c1: A_hi k0-7,k8-15 | c2,c3: A_lo | c4,c5: B_hi | c6,c7: B_lo
// Stage (32KB) = 2 sub-stages (k 0-15, k 16-31). 2 stages double-buffered = 64KB.
// 256 threads, 8 warps in 4x2 grid, warp tile 32x64 (R7 config).
#define BM 128
#define BN 128
#define SUB_BYTES 16384
#define STAGE_BYTES 32768

__device__ __forceinline__ void load_A16(float* f, const float* a) {
    const float4* p = (const float4*)a;
#pragma unroll
    for (int q = 0; q < 4; q++) {
        float4 v = p[q];
        f[4 * q] = v.x; f[4 * q + 1] = v.y; f[4 * q + 2] = v.z; f[4 * q + 3] = v.w;
    }
}
__device__ __forceinline__ void load_B16(float* f, const float* b, int stride) {
#pragma unroll
    for (int k = 0; k < 16; k++) f[k] = __ldg(b + (size_t)k * stride);
}

// convert 16 fp32 -> hi/lo bf16 chunks, store into sub-stage row r at chunk base cbase (0=A,4=B)
__device__ __forceinline__ void cvt_store_row(uint32_t sb, int r, int cbase, const float* f) {
    uint32_t rb = sb + (uint32_t)r * 128;
    uint32_t rx = (uint32_t)(r & 7);
#pragma unroll
    for (int half = 0; half < 2; half++) {
        uint32_t hi[4], lo[4];
#pragma unroll
        for (int q = 0; q < 4; q++) {
            float a = f[half * 8 + 2 * q], b = f[half * 8 + 2 * q + 1];
            uint32_t h = cvt2(a, b);
            float ha = __uint_as_float(h << 16);
            float hb = __uint_as_float(h & 0xFFFF0000u);
            hi[q] = h;
            lo[q] = cvt2(a - ha, b - hb);
        }
        uint32_t ah = rb + ((((uint32_t)(cbase + half)) ^ rx) << 4);
        uint32_t al = rb + ((((uint32_t)(cbase + 2 + half)) ^ rx) << 4);
        asm volatile("st.shared.v4.b32 [%0], {%1,%2,%3,%4};"
                     :: "r"(ah), "r"(hi[0]), "r"(hi[1]), "r"(hi[2]), "r"(hi[3]));
        asm volatile("st.shared.v4.b32 [%0], {%1,%2,%3,%4};"
                     :: "r"(al), "r"(lo[0]), "r"(lo[1]), "r"(lo[2]), "r"(lo[3]));
    }
}

// one k16 sub-stage; acc[16][4] = [mtile*8+ntile][frag]; warp tile 32x64.
// B fragments processed in QUARTERS (one ldsm pair live) to minimize registers.
__device__ __forceinline__ void compute_sub(uint32_t sb, float acc[16][4]) {
    int tid = threadIdx.x;
    int lane = tid & 31;
    int wid = tid >> 5;
    int wm = (wid & 3) * 32;
    int wn = (wid >> 2) * 64;
    int g = lane >> 3, lr = lane & 7;

    int aRow0 = wm + ((g & 1) << 3) + lr;
    uint32_t ah = (uint32_t)(g >> 1);
    int bRow0 = wn + ((g >> 1) << 3) + lr;
    uint32_t bh_ = (uint32_t)(g & 1);

    uint32_t Ah[2][4], Al[2][4];
#pragma unroll
    for (int t = 0; t < 2; t++) {
        uint32_t row = (uint32_t)(aRow0 + 16 * t);
        uint32_t rb = sb + row * 128, rx = row & 7;
        ldsm4(Ah[t], rb + (((0u + ah) ^ rx) << 4));
        ldsm4(Al[t], rb + (((2u + ah) ^ rx) << 4));
    }
#pragma unroll
    for (int q = 0; q < 4; q++) {
        uint32_t Bh[4], Bl[4];
        uint32_t row = (uint32_t)(bRow0 + 16 * q);
        uint32_t rb = sb + row * 128, rx = row & 7;
        ldsm4(Bh, rb + (((4u + bh_) ^ rx) << 4));
        ldsm4(Bl, rb + (((6u + bh_) ^ rx) << 4));
#pragma unroll
        for (int t = 0; t < 2; t++)
#pragma unroll
            for (int jj = 0; jj < 2; jj++) {
                float* c = acc[t * 8 + q * 2 + jj];
                mma_bf16(c, Ah[t], &Bh[jj * 2]);   // hi*hi
                mma_bf16(c, Ah[t], &Bl[jj * 2]);   // hi*lo
                mma_bf16(c, Al[t], &Bh[jj * 2]);   // lo*hi
            }
    }
}

// interleaved 32-k mainloop: load-early ordering hides LDG latency under MMA.
template <int KT2>
__device__ __forceinline__ void gemm_mainloop(uint32_t sbase, int r, bool isA,
                                              const float* srcA, const float* srcB, int strideB,
                                              float acc[16][4]) {
    int cbase = isA ? 0 : 4;
    {   // prologue: fill buffer 0 (both sub-stages)
        float f[16];
        if (isA) load_A16(f, srcA); else load_B16(f, srcB, strideB);
        cvt_store_row(sbase, r, cbase, f);
        if (isA) load_A16(f, srcA + 16); else load_B16(f, srcB + (size_t)16 * strideB, strideB);
        cvt_store_row(sbase + SUB_BYTES, r, cbase, f);
    }
    __syncthreads();
    for (int kt = 0; kt < KT2; kt++) {
        uint32_t cur = sbase + (uint32_t)(kt & 1) * STAGE_BYTES;
        uint32_t nxt = sbase + (uint32_t)((kt + 1) & 1) * STAGE_BYTES;
        bool more = (kt + 1 < KT2);
        float fn[16];
        int k0 = (kt + 1) * 32;
        if (more) {  // issue global loads; MMA below hides the latency
            if (isA) load_A16(fn, srcA + k0); else load_B16(fn, srcB + (size_t)k0 * strideB, strideB);
        }
        compute_sub(cur, acc);
        if (more) {
            cvt_store_row(nxt, r, cbase, fn);
            if (isA) load_A16(fn, srcA + k0 + 16);
            else     load_B16(fn, srcB + (size_t)(k0 + 16) * strideB, strideB);
        }
        compute_sub(cur + SUB_BYTES, acc);
        if (more) cvt_store_row(nxt + SUB_BYTES, r, cbase, fn);
        __syncthreads();
    }
}

// GEMM1: h = gelu(x[tok] @ W1[e] + b1) -> g_h (fp32)
__global__ __launch_bounds__(256, 2)
void gemm1_kernel(const float* __restrict__ x, const float* __restrict__ W1,
                  const float* __restrict__ b1) {
    __shared__ __align__(128) char smem[2 * STAGE_BYTES];
    int e = blockIdx.z;
    int cnt = g_cnt[e];
    int row0 = blockIdx.y * BM;
    if (row0 >= cnt) return;
    int col0 = blockIdx.x * BN;
    int off = g_off[e];
    int tid = threadIdx.x;
    uint32_t sbase = smem_u32(smem);

    int r = tid & 127;
    bool isA = tid < 128;
    const float* srcA = 0; const float* srcB = 0;
    if (isA) {
        int rA = min(row0 + r, cnt - 1);
        srcA = x + (size_t)g_tok[e * T_TOK + rA] * D_DIM;
    } else {
        srcB = W1 + (size_t)e * D_DIM * H_DIM + col0 + r;   // column (n), stride H_DIM over k
    }

    float acc[16][4];
#pragma unroll
    for (int i = 0; i < 16; i++)
#pragma unroll
        for (int j = 0; j < 4; j++) acc[i][j] = 0.0f;

    gemm_mainloop<D_DIM / 32>(sbase, r, isA, srcA, srcB, H_DIM, acc);

    // epilogue: bias + gelu -> g_h fp32
    int lane = tid & 31, wid = tid >> 5;
    int wm = (wid & 3) * 32, wn = (wid >> 2) * 64;
    int mrow = row0 + wm + (lane >> 2);
    int ncol = col0 + wn + (lane & 3) * 2;
    const float* bg = b1 + (size_t)e * H_DIM;

#pragma unroll
    for (int t = 0; t < 2; t++)
#pragma unroll
        for (int j = 0; j < 8; j++) {
            float* c = acc[t * 8 + j];
            int cc = ncol + j * 8;
            float bias0 = bg[cc], bias1 = bg[cc + 1];
            int r1 = mrow + t * 16, r2 = r1 + 8;
            if (r1 < cnt) {
                size_t o = (size_t)(off + r1) * H_DIM + cc;
                *(float2*)(g_h + o) = make_float2(gelu_exact(c[0] + bias0), gelu_exact(c[1] + bias1));
            }
            if (r2 < cnt) {
                size_t o = (size_t)(off + r2) * H_DIM + cc;
                *(float2*)(g_h + o) = make_float2(gelu_exact(c[2] + bias0), gelu_exact(c[3] + bias1));
            }
        }
}

// GEMM2: out[tok] += w * (h @ W2[e] + b2)
__global__ __launch_bounds__(256, 2)
void gemm2_kernel(const float* __restrict__ W2, const float* __restrict__ b2,
                  float* __restrict__ out) {
    __shared__ __align__(128) char smem[2 * STAGE_BYTES];
    int e = blockIdx.z;
    int cnt = g_cnt[e];
    int row0 = blockIdx.y * BM;
    if (row0 >= cnt) return;
    int col0 = blockIdx.x * BN;
    int off = g_off[e];
    int tid = threadIdx.x;
    uint32_t sbase = smem_u32(smem);

    int r = tid & 127;
    bool isA = tid < 128;
    const float* srcA = 0; const float* srcB = 0;
    if (isA) {
        int rA = off + min(row0 + r, cnt - 1);
        srcA = g_h + (size_t)rA * H_DIM;
    } else {
        srcB = W2 + (size_t)e * H_DIM * D_DIM + col0 + r;   // column (n), stride D_DIM over k
    }

    float acc[16][4];
#pragma unroll
    for (int i = 0; i < 16; i++)
#pragma unroll
        for (int j = 0; j < 4; j++) acc[i][j] = 0.0f;

    gemm_mainloop<H_DIM / 32>(sbase, r, isA, srcA, srcB, D_DIM, acc);

    int lane = tid & 31, wid = tid >> 5;
    int wm = (wid & 3) * 32, wn = (wid >> 2) * 64;
    int mrow = row0 + wm + (lane >> 2);
    int ncol = col0 + wn + (lane & 3) * 2;
    const float* bg = b2 + (size_t)e * D_DIM;

#pragma unroll
    for (int t = 0; t < 2; t++) {
        int r1 = mrow + t * 16, r2 = r1 + 8;
        int tok1 = 0, tok2 = 0; float w1 = 0.0f, w2 = 0.0f;
        if (r1 < cnt) { tok1 = g_tok[e * T_TOK + r1]; w1 = g_wt[e * T_TOK + r1]; }
        if (r2 < cnt) { tok2 = g_tok[e * T_TOK + r2]; w2 = g_wt[e * T_TOK + r2]; }
#pragma unroll
        for (int j = 0; j < 8; j++) {
            float* c = acc[t * 8 + j];
            int cc = ncol + j * 8;
            float bias0 = bg[cc], bias1 = bg[cc + 1];
            if (r1 < cnt) {
                float* o = out + (size_t)tok1 * D_DIM + cc;
                atomicAdd(o,     w1 * (c[0] + bias0));
                atomicAdd(o + 1, w1 * (c[1] + bias1));
            }
            if (r2 < cnt) {
                float* o = out + (size_t)tok2 * D_DIM + cc;
                atomicAdd(o,     w2 * (c[2] + bias0));
                atomicAdd(o + 1, w2 * (c[3] + bias1));
            }
        }
    }
}

// ---------------- launch ----------------
extern "C" void kernel_launch(void* const* d_in, const int* in_sizes, int n_in,
                              void* d_out, int out_size) {
    const float* x  = (const float*)d_in[0];
    const float* Wg = (const float*)d_in[1];
    const float* W1 = (const float*)d_in[2];
    const float* b1 = (const float*)d_in[3];
    const float* W2 = (const float*)d_in[4];
    const float* b2 = (const float*)d_in[5];
    float* out = (float*)d_out;

    zero_kernel<<<4096, 256>>>(out, out_size);
    router_kernel<<<T_TOK / 8, 256>>>(x, Wg);
    scan_kernel<<<1, 32>>>();

    gemm1_kernel<<<dim3(H_DIM / BN, T_TOK / BM, E_EXP), 256>>>(x, W1, b1);
    gemm2_kernel<<<dim3(D_DIM / BN, T_TOK / BM, E_EXP), 256>>>(W2, b2, out);
}

// round 10
// speedup vs baseline: 1.1510x; 1.0309x over previous
#include <cuda_runtime.h>
#include <cuda_bf16.h>
#include <math.h>
#include <stdint.h>

// Problem constants (fixed by the dataset)
#define T_TOK 8192
#define D_DIM 1024
#define E_EXP 8
#define H_DIM 4096

// ---------------- device-global scratch (keep total < ~256MB) ----------------
__device__ int   g_cnt[E_EXP];
__device__ int   g_off[E_EXP];
__device__ int   g_tok[E_EXP * T_TOK];
__device__ float g_wt [E_EXP * T_TOK];
__device__ __align__(256) __nv_bfloat16 g_xh[(size_t)T_TOK * D_DIM];       // 16MB
__device__ __align__(256) __nv_bfloat16 g_xl[(size_t)T_TOK * D_DIM];       // 16MB
__device__ __align__(256) __nv_bfloat16 g_hh[(size_t)T_TOK * 2 * H_DIM];   // 64MB
__device__ __align__(256) __nv_bfloat16 g_hl[(size_t)T_TOK * 2 * H_DIM];   // 64MB

// ---------------- helpers ----------------
__device__ __forceinline__ uint32_t smem_u32(const void* p) {
    uint32_t a;
    asm("{ .reg .u64 t; cvta.to.shared.u64 t, %1; cvt.u32.u64 %0, t; }" : "=r"(a) : "l"(p));
    return a;
}
__device__ __forceinline__ void ldsm4(uint32_t* r, uint32_t addr) {
    asm volatile("ldmatrix.sync.aligned.m8n8.x4.shared.b16 {%0,%1,%2,%3}, [%4];"
                 : "=r"(r[0]), "=r"(r[1]), "=r"(r[2]), "=r"(r[3]) : "r"(addr));
}
__device__ __forceinline__ void mma_bf16(float* c, const uint32_t* a, const uint32_t* b) {
    asm volatile("mma.sync.aligned.m16n8k16.row.col.f32.bf16.bf16.f32 "
                 "{%0,%1,%2,%3}, {%4,%5,%6,%7}, {%8,%9}, {%0,%1,%2,%3};"
                 : "+f"(c[0]), "+f"(c[1]), "+f"(c[2]), "+f"(c[3])
                 : "r"(a[0]), "r"(a[1]), "r"(a[2]), "r"(a[3]), "r"(b[0]), "r"(b[1]));
}
__device__ __forceinline__ void cp16(uint32_t s, const void* g) {
    asm volatile("cp.async.cg.shared.global [%0], [%1], 16;" :: "r"(s), "l"(g) : "memory");
}
#define CP_COMMIT() asm volatile("cp.async.commit_group;" ::: "memory")
#define CP_WAIT0()  asm volatile("cp.async.wait_group 0;" ::: "memory")

// pack {lo=bf16(a), hi=bf16(b)} in one cvt
__device__ __forceinline__ uint32_t cvt2(float a, float b) {
    uint32_t r;
    asm("cvt.rn.bf16x2.f32 %0, %1, %2;" : "=r"(r) : "f"(b), "f"(a));
    return r;
}
__device__ __forceinline__ float gelu_exact(float v) {
    return 0.5f * v * (1.0f + erff(v * 0.70710678118654752f));
}

// ---------------- small kernels (R1-proven) ----------------
__global__ void zero_kernel(float* __restrict__ out, int n) {
    int i = blockIdx.x * blockDim.x + threadIdx.x;
    if (i < E_EXP) g_cnt[i] = 0;
    for (int j = i; j < n; j += gridDim.x * blockDim.x) out[j] = 0.0f;
}

__global__ void router_kernel(const float* __restrict__ x, const float* __restrict__ Wg) {
    int warp = (blockIdx.x * blockDim.x + threadIdx.x) >> 5;
    int lane = threadIdx.x & 31;
    if (warp >= T_TOK) return;
    const float* xr = x + (size_t)warp * D_DIM;
    float acc[E_EXP];
#pragma unroll
    for (int e = 0; e < E_EXP; e++) acc[e] = 0.0f;
    for (int k = lane; k < D_DIM; k += 32) {
        float xv = xr[k];
        const float* wr = Wg + (size_t)k * E_EXP;
#pragma unroll
        for (int e = 0; e < E_EXP; e++) acc[e] = fmaf(xv, wr[e], acc[e]);
    }
#pragma unroll
    for (int e = 0; e < E_EXP; e++)
#pragma unroll
        for (int o = 16; o > 0; o >>= 1) acc[e] += __shfl_xor_sync(0xffffffffu, acc[e], o);
    if (lane == 0) {
        float mx = acc[0];
#pragma unroll
        for (int e = 1; e < E_EXP; e++) mx = fmaxf(mx, acc[e]);
        float p[E_EXP], s = 0.0f;
#pragma unroll
        for (int e = 0; e < E_EXP; e++) { p[e] = expf(acc[e] - mx); s += p[e]; }
        float inv = 1.0f / s;
        int i1 = 0; float v1 = p[0];
#pragma unroll
        for (int e = 1; e < E_EXP; e++) if (p[e] > v1) { v1 = p[e]; i1 = e; }
        int i2 = -1; float v2 = -1.0f;
#pragma unroll
        for (int e = 0; e < E_EXP; e++) if (e != i1 && p[e] > v2) { v2 = p[e]; i2 = e; }
        int p1 = atomicAdd(&g_cnt[i1], 1);
        g_tok[i1 * T_TOK + p1] = warp; g_wt[i1 * T_TOK + p1] = v1 * inv;
        int p2 = atomicAdd(&g_cnt[i2], 1);
        g_tok[i2 * T_TOK + p2] = warp; g_wt[i2 * T_TOK + p2] = v2 * inv;
    }
}

__global__ void scan_kernel() {
    if (threadIdx.x == 0) {
        int s = 0;
#pragma unroll
        for (int e = 0; e < E_EXP; e++) { g_off[e] = s; s += g_cnt[e]; }
    }
}

// split x (fp32 -> bf16 hi/lo), identical arithmetic to the inline split
__global__ void split_x_kernel(const float* __restrict__ x) {
    int i = blockIdx.x * blockDim.x + threadIdx.x;
    int n4 = (T_TOK * D_DIM) / 4;
    if (i >= n4) return;
    float4 v = ((const float4*)x)[i];
    uint32_t h0 = cvt2(v.x, v.y), h1 = cvt2(v.z, v.w);
    float a0 = __uint_as_float(h0 << 16), b0 = __uint_as_float(h0 & 0xFFFF0000u);
    float a1 = __uint_as_float(h1 << 16), b1 = __uint_as_float(h1 & 0xFFFF0000u);
    uint2 hp = make_uint2(h0, h1);
    uint2 lp = make_uint2(cvt2(v.x - a0, v.y - b0), cvt2(v.z - a1, v.w - b1));
    ((uint2*)g_xh)[i] = hp;
    ((uint2*)g_xl)[i] = lp;
}

// ---------------- HMMA GEMM ----------------
// Sub-stage (16KB): 128 rows x 128B. Row r, 8 chunks of 16B at slot ((c ^ (r&7)) << 4):
//   c0,c1: A_hi k0-7,k8-15 | c2,c3: A_lo | c4,c5: B_hi | c6,c7: B_lo
// A path: cp.async 16B chunks from pre-split bf16 (no reg round-trip, no cvt).
// B path: inline fp32 LDG -> cvt -> STS (R9-proven).
#define BM 128
#define BN 128
#define SUB_BYTES 16384
#define STAGE_BYTES 32768

__device__ __forceinline__ void load_B16(float* f, const float* b, int stride) {
#pragma unroll
    for (int k = 0; k < 16; k++) f[k] = __ldg(b + (size_t)k * stride);
}

// convert 16 fp32 -> hi/lo bf16, store into sub-stage row r at chunk base 4 (B slots)
__device__ __forceinline__ void cvt_store_rowB(uint32_t sb, int r, const float* f) {
    uint32_t rb = sb + (uint32_t)r * 128;
    uint32_t rx = (uint32_t)(r & 7);
#pragma unroll
    for (int half = 0; half < 2; half++) {
        uint32_t hi[4], lo[4];
#pragma unroll
        for (int q = 0; q < 4; q++) {
            float a = f[half * 8 + 2 * q], b = f[half * 8 + 2 * q + 1];
            uint32_t h = cvt2(a, b);
            float ha = __uint_as_float(h << 16);
            float hb = __uint_as_float(h & 0xFFFF0000u);
            hi[q] = h;
            lo[q] = cvt2(a - ha, b - hb);
        }
        uint32_t ah = rb + ((((uint32_t)(4 + half)) ^ rx) << 4);
        uint32_t al = rb + ((((uint32_t)(6 + half)) ^ rx) << 4);
        asm volatile("st.shared.v4.b32 [%0], {%1,%2,%3,%4};"
                     :: "r"(ah), "r"(hi[0]), "r"(hi[1]), "r"(hi[2]), "r"(hi[3]));
        asm volatile("st.shared.v4.b32 [%0], {%1,%2,%3,%4};"
                     :: "r"(al), "r"(lo[0]), "r"(lo[1]), "r"(lo[2]), "r"(lo[3]));
    }
}

// cp.async row r's A chunks for one k16 sub-stage. kb = byte offset (k0*2).
__device__ __forceinline__ void cpA_row(uint32_t sb, int r, const char* ah, const char* al, size_t kb) {
    uint32_t rb = sb + (uint32_t)r * 128;
    uint32_t rx = (uint32_t)(r & 7);
    cp16(rb + ((0u ^ rx) << 4), ah + kb);
    cp16(rb + ((1u ^ rx) << 4), ah + kb + 16);
    cp16(rb + ((2u ^ rx) << 4), al + kb);
    cp16(rb + ((3u ^ rx) << 4), al + kb + 16);
}

// one k16 sub-stage; acc[16][4] = [mtile*8+ntile][frag]; warp tile 32x64.
__device__ __forceinline__ void compute_sub(uint32_t sb, float acc[16][4]) {
    int tid = threadIdx.x;
    int lane = tid & 31;
    int wid = tid >> 5;
    int wm = (wid & 3) * 32;
    int wn = (wid >> 2) * 64;
    int g = lane >> 3, lr = lane & 7;

    int aRow0 = wm + ((g & 1) << 3) + lr;
    uint32_t ah = (uint32_t)(g >> 1);
    int bRow0 = wn + ((g >> 1) << 3) + lr;
    uint32_t bh_ = (uint32_t)(g & 1);

    uint32_t Ah[2][4], Al[2][4];
#pragma unroll
    for (int t = 0; t < 2; t++) {
        uint32_t row = (uint32_t)(aRow0 + 16 * t);
        uint32_t rb = sb + row * 128, rx = row & 7;
        ldsm4(Ah[t], rb + (((0u + ah) ^ rx) << 4));
        ldsm4(Al[t], rb + (((2u + ah) ^ rx) << 4));
    }
#pragma unroll
    for (int q = 0; q < 4; q++) {
        uint32_t Bh[4], Bl[4];
        uint32_t row = (uint32_t)(bRow0 + 16 * q);
        uint32_t rb = sb + row * 128, rx = row & 7;
        ldsm4(Bh, rb + (((4u + bh_) ^ rx) << 4));
        ldsm4(Bl, rb + (((6u + bh_) ^ rx) << 4));
#pragma unroll
        for (int t = 0; t < 2; t++)
#pragma unroll
            for (int jj = 0; jj < 2; jj++) {
                float* c = acc[t * 8 + q * 2 + jj];
                mma_bf16(c, Ah[t], &Bh[jj * 2]);   // hi*hi
                mma_bf16(c, Ah[t], &Bl[jj * 2]);   // hi*lo
                mma_bf16(c, Al[t], &Bh[jj * 2]);   // lo*hi
            }
    }
}

// interleaved 32-k mainloop; A via cp.async (bf16 pre-split), B inline fp32.
template <int KT2>
__device__ __forceinline__ void gemm_mainloop(uint32_t sbase, int r, bool isA,
                                              const char* srcAh, const char* srcAl,
                                              const float* srcB, int strideB,
                                              float acc[16][4]) {
    {   // prologue: fill buffer 0 (both sub-stages)
        if (isA) {
            cpA_row(sbase, r, srcAh, srcAl, 0);
            cpA_row(sbase + SUB_BYTES, r, srcAh, srcAl, 32);
            CP_COMMIT();
        } else {
            float f[16];
            load_B16(f, srcB, strideB);
            cvt_store_rowB(sbase, r, f);
            load_B16(f, srcB + (size_t)16 * strideB, strideB);
            cvt_store_rowB(sbase + SUB_BYTES, r, f);
        }
    }
    CP_WAIT0();
    __syncthreads();
    for (int kt = 0; kt < KT2; kt++) {
        uint32_t cur = sbase + (uint32_t)(kt & 1) * STAGE_BYTES;
        uint32_t nxt = sbase + (uint32_t)((kt + 1) & 1) * STAGE_BYTES;
        bool more = (kt + 1 < KT2);
        float fn[16];
        int k0 = (kt + 1) * 32;
        if (more) {  // issue next-buffer loads; MMAs below hide the latency
            if (isA) { cpA_row(nxt, r, srcAh, srcAl, (size_t)k0 * 2); CP_COMMIT(); }
            else     load_B16(fn, srcB + (size_t)k0 * strideB, strideB);
        }
        compute_sub(cur, acc);
        if (more) {
            if (isA) { cpA_row(nxt + SUB_BYTES, r, srcAh, srcAl, (size_t)(k0 + 16) * 2); CP_COMMIT(); }
            else {
                cvt_store_rowB(nxt, r, fn);
                load_B16(fn, srcB + (size_t)(k0 + 16) * strideB, strideB);
            }
        }
        compute_sub(cur + SUB_BYTES, acc);
        if (more && !isA) cvt_store_rowB(nxt + SUB_BYTES, r, fn);
        CP_WAIT0();
        __syncthreads();
    }
}

// GEMM1: h = gelu(x[tok] @ W1[e] + b1) -> g_hh/g_hl (bf16 hi/lo)
__global__ __launch_bounds__(256, 2)
void gemm1_kernel(const float* __restrict__ W1, const float* __restrict__ b1) {
    __shared__ __align__(128) char smem[2 * STAGE_BYTES];
    int e = blockIdx.z;
    int cnt = g_cnt[e];
    int row0 = blockIdx.y * BM;
    if (row0 >= cnt) return;
    int col0 = blockIdx.x * BN;
    int off = g_off[e];
    int tid = threadIdx.x;
    uint32_t sbase = smem_u32(smem);

    int r = tid & 127;
    bool isA = tid < 128;
    const char* srcAh = 0; const char* srcAl = 0; const float* srcB = 0;
    if (isA) {
        int rA = min(row0 + r, cnt - 1);
        size_t rowOff = (size_t)g_tok[e * T_TOK + rA] * D_DIM * 2;
        srcAh = (const char*)g_xh + rowOff;
        srcAl = (const char*)g_xl + rowOff;
    } else {
        srcB = W1 + (size_t)e * D_DIM * H_DIM + col0 + r;   // column (n), stride H_DIM over k
    }

    float acc[16][4];
#pragma unroll
    for (int i = 0; i < 16; i++)
#pragma unroll
        for (int j = 0; j < 4; j++) acc[i][j] = 0.0f;

    gemm_mainloop<D_DIM / 32>(sbase, r, isA, srcAh, srcAl, srcB, H_DIM, acc);

    // epilogue: bias + gelu -> bf16 hi/lo scratch
    int lane = tid & 31, wid = tid >> 5;
    int wm = (wid & 3) * 32, wn = (wid >> 2) * 64;
    int mrow = row0 + wm + (lane >> 2);
    int ncol = col0 + wn + (lane & 3) * 2;
    const float* bg = b1 + (size_t)e * H_DIM;

#pragma unroll
    for (int t = 0; t < 2; t++)
#pragma unroll
        for (int j = 0; j < 8; j++) {
            float* c = acc[t * 8 + j];
            int cc = ncol + j * 8;
            float bias0 = bg[cc], bias1 = bg[cc + 1];
            int r1 = mrow + t * 16, r2 = r1 + 8;
            if (r1 < cnt) {
                float g0 = gelu_exact(c[0] + bias0), g1 = gelu_exact(c[1] + bias1);
                uint32_t h = cvt2(g0, g1);
                float ha = __uint_as_float(h << 16), hb = __uint_as_float(h & 0xFFFF0000u);
                size_t o = (size_t)(off + r1) * H_DIM + cc;
                *(uint32_t*)(g_hh + o) = h;
                *(uint32_t*)(g_hl + o) = cvt2(g0 - ha, g1 - hb);
            }
            if (r2 < cnt) {
                float g0 = gelu_exact(c[2] + bias0), g1 = gelu_exact(c[3] + bias1);
                uint32_t h = cvt2(g0, g1);
                float ha = __uint_as_float(h << 16), hb = __uint_as_float(h & 0xFFFF0000u);
                size_t o = (size_t)(off + r2) * H_DIM + cc;
                *(uint32_t*)(g_hh + o) = h;
                *(uint32_t*)(g_hl + o) = cvt2(g0 - ha, g1 - hb);
            }
        }
}

// GEMM2: out[tok] += w * (h @ W2[e] + b2)
__global__ __launch_bounds__(256, 2)
void gemm2_kernel(const float* __restrict__ W2, const float* __restrict__ b2,
                  float* __restrict__ out) {
    __shared__ __align__(128) char smem[2 * STAGE_BYTES];
    int e = blockIdx.z;
    int cnt = g_cnt[e];
    int row0 = blockIdx.y * BM;
    if (row0 >= cnt) return;
    int col0 = blockIdx.x * BN;
    int off = g_off[e];
    int tid = threadIdx.x;
    uint32_t sbase = smem_u32(smem);

    int r = tid & 127;
    bool isA = tid < 128;
    const char* srcAh = 0; const char* srcAl = 0; const float* srcB = 0;
    if (isA) {
        int rA = off + min(row0 + r, cnt - 1);
        size_t rowOff = (size_t)rA * H_DIM * 2;
        srcAh = (const char*)g_hh + rowOff;
        srcAl = (const char*)g_hl + rowOff;
    } else {
        srcB = W2 + (size_t)e * H_DIM * D_DIM + col0 + r;   // column (n), stride D_DIM over k
    }

    float acc[16][4];
#pragma unroll
    for (int i = 0; i < 16; i++)
#pragma unroll
        for (int j = 0; j < 4; j++) acc[i][j] = 0.0f;

    gemm_mainloop<H_DIM / 32>(sbase, r, isA, srcAh, srcAl, srcB, D_DIM, acc);

    int lane = tid & 31, wid = tid >> 5;
    int wm = (wid & 3) * 32, wn = (wid >> 2) * 64;
    int mrow = row0 + wm + (lane >> 2);
    int ncol = col0 + wn + (lane & 3) * 2;
    const float* bg = b2 + (size_t)e * D_DIM;

#pragma unroll
    for (int t = 0; t < 2; t++) {
        int r1 = mrow + t * 16, r2 = r1 + 8;
        int tok1 = 0, tok2 = 0; float w1 = 0.0f, w2 = 0.0f;
        if (r1 < cnt) { tok1 = g_tok[e * T_TOK + r1]; w1 = g_wt[e * T_TOK + r1]; }
        if (r2 < cnt) { tok2 = g_tok[e * T_TOK + r2]; w2 = g_wt[e * T_TOK + r2]; }
#pragma unroll
        for (int j = 0; j < 8; j++) {
            float* c = acc[t * 8 + j];
            int cc = ncol + j * 8;
            float bias0 = bg[cc], bias1 = bg[cc + 1];
            if (r1 < cnt) {
                float* o = out + (size_t)tok1 * D_DIM + cc;
                atomicAdd(o,     w1 * (c[0] + bias0));
                atomicAdd(o + 1, w1 * (c[1] + bias1));
            }
            if (r2 < cnt) {
                float* o = out + (size_t)tok2 * D_DIM + cc;
                atomicAdd(o,     w2 * (c[2] + bias0));
                atomicAdd(o + 1, w2 * (c[3] + bias1));
            }
        }
    }
}

// ---------------- launch ----------------
extern "C" void kernel_launch(void* const* d_in, const int* in_sizes, int n_in,
                              void* d_out, int out_size) {
    const float* x  = (const float*)d_in[0];
    const float* Wg = (const float*)d_in[1];
    const float* W1 = (const float*)d_in[2];
    const float* b1 = (const float*)d_in[3];
    const float* W2 = (const float*)d_in[4];
    const float* b2 = (const float*)d_in[5];
    float* out = (float*)d_out;

    zero_kernel<<<4096, 256>>>(out, out_size);
    router_kernel<<<T_TOK / 8, 256>>>(x, Wg);
    scan_kernel<<<1, 32>>>();
    split_x_kernel<<<(T_TOK * D_DIM / 4 + 255) / 256, 256>>>(x);

    gemm1_kernel<<<dim3(H_DIM / BN, T_TOK / BM, E_EXP), 256>>>(W1, b1);
    gemm2_kernel<<<dim3(D_DIM / BN, T_TOK / BM, E_EXP), 256>>>(W2, b2, out);
}